// round 10
// baseline (speedup 1.0000x reference)
#include <cuda_runtime.h>

#define TT   300
#define LSEQ 30
#define CH   128
#define NS   16
#define NR   8
#define NBLK (8 * 300)

// Precomputed fused epilogue weights: M_dir = Wout_dir @ comb_W_half, and
// constant vector cvec = comb_b + f_bout@comb_W[:128] + b_bout@comb_W[128:].
__device__ float g_Mf[CH * CH];
__device__ float g_Mb[CH * CH];
__device__ float g_cvec[CH];

struct DirParams {
    const float *Win, *bin, *convw, *convb, *Wx, *Wdt, *bdt, *Alog, *D;
};

struct KParams {
    const float *x, *ln_g, *ln_b;
    DirParams dp[2];
    float *out;
};

// ---------------------------------------------------------------------------
// Precompute kernel: M_f[d][c] = sum_j Wout_f[d][j] * comb_W[j][c]
//                    M_b[d][c] = sum_j Wout_b[d][j] * comb_W[128+j][c]
// ---------------------------------------------------------------------------
__global__ void precompute_kernel(const float* __restrict__ fWout,
                                  const float* __restrict__ bWout,
                                  const float* __restrict__ combW,
                                  const float* __restrict__ combb,
                                  const float* __restrict__ fbout,
                                  const float* __restrict__ bbout) {
    int dd = blockIdx.x;
    int c  = threadIdx.x;
    float af = 0.f, ab = 0.f;
    for (int j = 0; j < CH; ++j) {
        float cw_top = combW[j * CH + c];
        float cw_bot = combW[(CH + j) * CH + c];
        af = fmaf(fWout[dd * CH + j], cw_top, af);
        ab = fmaf(bWout[dd * CH + j], cw_bot, ab);
    }
    g_Mf[dd * CH + c] = af;
    g_Mb[dd * CH + c] = ab;
    if (dd == 0) {
        float cv = combb[c];
        for (int j = 0; j < CH; ++j) {
            cv = fmaf(fbout[j], combW[j * CH + c], cv);
            cv = fmaf(bbout[j], combW[(CH + j) * CH + c], cv);
        }
        g_cvec[c] = cv;
    }
}

// ---------------------------------------------------------------------------
// Per-direction processing. BACK=true runs the backward (flipped) direction
// without physically flipping data: anti-causal conv + reverse-order scan.
// ---------------------------------------------------------------------------
template <bool BACK>
__device__ __forceinline__ void process_dir(const DirParams& P,
                                            const float* __restrict__ Mfused,
                                            float* s_xn, float* s_xp,
                                            float* s_y, float* s_xdbl,
                                            float* s_acc, int d) {
    const float* __restrict__ Win = P.Win;
    float zreg[LSEQ];  // silu(z), kept in registers (static-index only)

    // ---- xz = xn @ Win + bin ; xp -> smem, silu(z) -> regs -----------------
    const float binx = P.bin[d];
    const float binz = P.bin[CH + d];
#pragma unroll
    for (int chunk = 0; chunk < 2; ++chunk) {
        float ax[15], az[15];
#pragma unroll
        for (int i = 0; i < 15; ++i) { ax[i] = 0.f; az[i] = 0.f; }
        const float4* xn4 =
            reinterpret_cast<const float4*>(s_xn + chunk * 15 * CH);
        for (int c4 = 0; c4 < 32; ++c4) {
            const float* wp = Win + c4 * 4 * 256 + d;
            float wx0 = wp[0];         float wz0 = wp[128];
            float wx1 = wp[256];       float wz1 = wp[256 + 128];
            float wx2 = wp[512];       float wz2 = wp[512 + 128];
            float wx3 = wp[768];       float wz3 = wp[768 + 128];
#pragma unroll
            for (int i = 0; i < 15; ++i) {
                float4 v = xn4[i * 32 + c4];
                ax[i] = fmaf(v.x, wx0, ax[i]); az[i] = fmaf(v.x, wz0, az[i]);
                ax[i] = fmaf(v.y, wx1, ax[i]); az[i] = fmaf(v.y, wz1, az[i]);
                ax[i] = fmaf(v.z, wx2, ax[i]); az[i] = fmaf(v.z, wz2, az[i]);
                ax[i] = fmaf(v.w, wx3, ax[i]); az[i] = fmaf(v.w, wz3, az[i]);
            }
        }
#pragma unroll
        for (int i = 0; i < 15; ++i) {
            int l = chunk * 15 + i;
            s_xp[l * CH + d] = ax[i] + binx;
            float zv = az[i] + binz;
            zreg[l] = zv / (1.f + __expf(-zv));
        }
    }

    // ---- depthwise causal conv + silu (own column only, no sync needed) ---
    {
        float cw0 = P.convw[d * 4 + 0], cw1 = P.convw[d * 4 + 1];
        float cw2 = P.convw[d * 4 + 2], cw3 = P.convw[d * 4 + 3];
        float cb = P.convb[d];
        if (!BACK) {
            float w0 = 0.f, w1 = 0.f, w2 = 0.f;
#pragma unroll
            for (int l = 0; l < LSEQ; ++l) {
                float cur = s_xp[l * CH + d];
                float xc = cb + cw0 * w0 + cw1 * w1 + cw2 * w2 + cw3 * cur;
                w0 = w1; w1 = w2; w2 = cur;
                s_xp[l * CH + d] = xc / (1.f + __expf(-xc));
            }
        } else {
            // flipped causal conv == anti-causal conv with reversed taps
            float f1 = 0.f, f2 = 0.f, f3 = 0.f;
#pragma unroll
            for (int l = LSEQ - 1; l >= 0; --l) {
                float cur = s_xp[l * CH + d];
                float xc = cb + cw3 * cur + cw2 * f1 + cw1 * f2 + cw0 * f3;
                f3 = f2; f2 = f1; f1 = cur;
                s_xp[l * CH + d] = xc / (1.f + __expf(-xc));
            }
        }
    }
    __syncthreads();

    // ---- xdbl = xp @ Wx  (40 output cols: dtr[8] | B[16] | C[16]) ----------
    if (d < 120) {
        int g = d / 40, col = d % 40;
        const float* __restrict__ Wx = P.Wx;
        float acc[10];
#pragma unroll
        for (int i = 0; i < 10; ++i) acc[i] = 0.f;
        const float4* xp4 =
            reinterpret_cast<const float4*>(s_xp + g * 10 * CH);
        for (int c4 = 0; c4 < 32; ++c4) {
            float w0 = Wx[(c4 * 4 + 0) * 40 + col];
            float w1 = Wx[(c4 * 4 + 1) * 40 + col];
            float w2 = Wx[(c4 * 4 + 2) * 40 + col];
            float w3 = Wx[(c4 * 4 + 3) * 40 + col];
#pragma unroll
            for (int i = 0; i < 10; ++i) {
                float4 v = xp4[i * 32 + c4];
                acc[i] = fmaf(v.x, w0,
                         fmaf(v.y, w1, fmaf(v.z, w2, fmaf(v.w, w3, acc[i]))));
            }
        }
#pragma unroll
        for (int i = 0; i < 10; ++i)
            s_xdbl[(g * 10 + i) * 40 + col] = acc[i];
    }
    __syncthreads();

    // ---- dt = softplus(dtr @ Wdt + bdt), staged into s_y -------------------
    {
        float wdt[NR];
#pragma unroll
        for (int r = 0; r < NR; ++r) wdt[r] = P.Wdt[r * CH + d];
        float bdtv = P.bdt[d];
#pragma unroll
        for (int l = 0; l < LSEQ; ++l) {
            const float4* row =
                reinterpret_cast<const float4*>(s_xdbl + l * 40);
            float4 r0 = row[0], r1 = row[1];
            float acc = bdtv;
            acc = fmaf(r0.x, wdt[0], acc); acc = fmaf(r0.y, wdt[1], acc);
            acc = fmaf(r0.z, wdt[2], acc); acc = fmaf(r0.w, wdt[3], acc);
            acc = fmaf(r1.x, wdt[4], acc); acc = fmaf(r1.y, wdt[5], acc);
            acc = fmaf(r1.z, wdt[6], acc); acc = fmaf(r1.w, wdt[7], acc);
            s_y[l * CH + d] = (acc > 20.f) ? acc : log1pf(__expf(acc));
        }
    }

    // ---- selective scan (sequential over L, 16 states in registers) -------
    {
        float Areg[NS];
#pragma unroll
        for (int s = 0; s < NS; ++s) Areg[s] = -expf(P.Alog[d * NS + s]);
        float Dp = P.D[d];
        float h[NS];
#pragma unroll
        for (int s = 0; s < NS; ++s) h[s] = 0.f;
        for (int it = 0; it < LSEQ; ++it) {
            int l = BACK ? (LSEQ - 1 - it) : it;
            float dt_t = s_y[l * CH + d];     // staged dt
            float x_t  = s_xp[l * CH + d];
            float dtx  = dt_t * x_t;
            const float4* bc =
                reinterpret_cast<const float4*>(s_xdbl + l * 40 + 8);
            float4 B0 = bc[0], B1 = bc[1], B2 = bc[2], B3 = bc[3];
            float4 C0 = bc[4], C1 = bc[5], C2 = bc[6], C3 = bc[7];
            float y = 0.f;
#define SSTEP(s, Bv, Cv)                                 \
    {                                                    \
        float dA_ = __expf(dt_t * Areg[s]);              \
        h[s] = fmaf(dA_, h[s], dtx * (Bv));              \
        y = fmaf(h[s], (Cv), y);                         \
    }
            SSTEP(0,  B0.x, C0.x) SSTEP(1,  B0.y, C0.y)
            SSTEP(2,  B0.z, C0.z) SSTEP(3,  B0.w, C0.w)
            SSTEP(4,  B1.x, C1.x) SSTEP(5,  B1.y, C1.y)
            SSTEP(6,  B1.z, C1.z) SSTEP(7,  B1.w, C1.w)
            SSTEP(8,  B2.x, C2.x) SSTEP(9,  B2.y, C2.y)
            SSTEP(10, B2.z, C2.z) SSTEP(11, B2.w, C2.w)
            SSTEP(12, B3.x, C3.x) SSTEP(13, B3.y, C3.y)
            SSTEP(14, B3.z, C3.z) SSTEP(15, B3.w, C3.w)
#undef SSTEP
            s_y[l * CH + d] = fmaf(x_t, Dp, y);  // + skip via D
        }
    }

    // ---- gate by silu(z) (static-index loop keeps zreg in regs) -----------
#pragma unroll
    for (int l = 0; l < LSEQ; ++l) s_y[l * CH + d] *= zreg[l];
    __syncthreads();

    // ---- fused epilogue: s_acc += s_y @ (Wout @ comb_half) ----------------
#pragma unroll
    for (int chunk = 0; chunk < 2; ++chunk) {
        float a[15];
#pragma unroll
        for (int i = 0; i < 15; ++i)
            a[i] = s_acc[(chunk * 15 + i) * CH + d];
        const float4* y4 =
            reinterpret_cast<const float4*>(s_y + chunk * 15 * CH);
        for (int j4 = 0; j4 < 32; ++j4) {
            const float* mp = Mfused + j4 * 4 * CH + d;
            float m0 = mp[0], m1 = mp[CH], m2 = mp[2 * CH], m3 = mp[3 * CH];
#pragma unroll
            for (int i = 0; i < 15; ++i) {
                float4 v = y4[i * 32 + j4];
                a[i] = fmaf(v.x, m0,
                       fmaf(v.y, m1, fmaf(v.z, m2, fmaf(v.w, m3, a[i]))));
            }
        }
#pragma unroll
        for (int i = 0; i < 15; ++i)
            s_acc[(chunk * 15 + i) * CH + d] = a[i];
    }
    __syncthreads();
}

// ---------------------------------------------------------------------------
// Main kernel: one block per (b, t) frame.
// smem: acc[30*128] | xn[30*128] | xp[30*128] | y[30*128] | xdbl[30*40]
// ---------------------------------------------------------------------------
__global__ void __launch_bounds__(128, 3)
mamba_main(KParams P) {
    extern __shared__ float smem[];
    float* s_acc  = smem;              // raw input -> final accumulator
    float* s_xn   = smem + 3840;       // normalized input
    float* s_xp   = smem + 7680;       // xp (pre/post conv+silu)
    float* s_y    = smem + 11520;      // dt staging -> gated scan output
    float* s_xdbl = smem + 15360;      // [30][40] : dtr | B | C

    const int d  = threadIdx.x;
    const int bt = blockIdx.x;
    const int b  = bt / TT;
    const int t  = bt % TT;

    // ---- load x[b, d, t, :] (30 contiguous floats per thread) -------------
    const float2* x2 = reinterpret_cast<const float2*>(
        P.x + ((size_t)(b * CH + d) * TT + t) * LSEQ);
#pragma unroll
    for (int i = 0; i < 15; ++i) {
        float2 v = x2[i];
        s_acc[(2 * i) * CH + d]     = v.x;
        s_acc[(2 * i + 1) * CH + d] = v.y;
    }
    __syncthreads();

    // ---- LayerNorm over the 128 channels of each row -----------------------
    {
        int warp = d >> 5, lane = d & 31;
        float g0 = P.ln_g[lane],      g1 = P.ln_g[lane + 32];
        float g2 = P.ln_g[lane + 64], g3 = P.ln_g[lane + 96];
        float e0 = P.ln_b[lane],      e1 = P.ln_b[lane + 32];
        float e2 = P.ln_b[lane + 64], e3 = P.ln_b[lane + 96];
        for (int l = warp; l < LSEQ; l += 4) {
            float v0 = s_acc[l * CH + lane];
            float v1 = s_acc[l * CH + lane + 32];
            float v2 = s_acc[l * CH + lane + 64];
            float v3 = s_acc[l * CH + lane + 96];
            float sum = v0 + v1 + v2 + v3;
            float sq  = v0 * v0 + v1 * v1 + v2 * v2 + v3 * v3;
#pragma unroll
            for (int off = 16; off > 0; off >>= 1) {
                sum += __shfl_xor_sync(0xffffffffu, sum, off);
                sq  += __shfl_xor_sync(0xffffffffu, sq, off);
            }
            float mu  = sum * (1.f / 128.f);
            float var = sq * (1.f / 128.f) - mu * mu;
            float rs  = rsqrtf(var + 1e-5f);
            s_xn[l * CH + lane]      = (v0 - mu) * rs * g0 + e0;
            s_xn[l * CH + lane + 32] = (v1 - mu) * rs * g1 + e1;
            s_xn[l * CH + lane + 64] = (v2 - mu) * rs * g2 + e2;
            s_xn[l * CH + lane + 96] = (v3 - mu) * rs * g3 + e3;
        }
    }
    __syncthreads();

    process_dir<false>(P.dp[0], g_Mf, s_xn, s_xp, s_y, s_xdbl, s_acc, d);
    process_dir<true >(P.dp[1], g_Mb, s_xn, s_xp, s_y, s_xdbl, s_acc, d);

    // ---- write out (+ fused bias vector) -----------------------------------
    float cv = g_cvec[d];
    float2* o2 = reinterpret_cast<float2*>(
        P.out + ((size_t)(b * CH + d) * TT + t) * LSEQ);
#pragma unroll
    for (int i = 0; i < 15; ++i) {
        float2 v;
        v.x = s_acc[(2 * i) * CH + d] + cv;
        v.y = s_acc[(2 * i + 1) * CH + d] + cv;
        o2[i] = v;
    }
}

// ---------------------------------------------------------------------------
extern "C" void kernel_launch(void* const* d_in, const int* in_sizes, int n_in,
                              void* d_out, int out_size) {
    (void)in_sizes; (void)n_in; (void)out_size;
    KParams P;
    P.x    = (const float*)d_in[0];
    P.ln_g = (const float*)d_in[1];
    P.ln_b = (const float*)d_in[2];
    for (int dir = 0; dir < 2; ++dir) {
        int o = 3 + dir * 11;
        P.dp[dir].Win   = (const float*)d_in[o + 0];
        P.dp[dir].bin   = (const float*)d_in[o + 1];
        P.dp[dir].convw = (const float*)d_in[o + 2];
        P.dp[dir].convb = (const float*)d_in[o + 3];
        P.dp[dir].Wx    = (const float*)d_in[o + 4];
        P.dp[dir].Wdt   = (const float*)d_in[o + 5];
        P.dp[dir].bdt   = (const float*)d_in[o + 6];
        P.dp[dir].Alog  = (const float*)d_in[o + 7];
        P.dp[dir].D     = (const float*)d_in[o + 8];
        // [o+9] = Wout, [o+10] = bout -> consumed by precompute_kernel
    }
    P.out = (float*)d_out;

    // Fuse Wout @ comb_W halves (+ bias folding) once per launch.
    precompute_kernel<<<CH, CH>>>(
        (const float*)d_in[12], (const float*)d_in[23],
        (const float*)d_in[25], (const float*)d_in[26],
        (const float*)d_in[13], (const float*)d_in[24]);

    const int smem_bytes = 16560 * sizeof(float);  // 66240 B
    cudaFuncSetAttribute(mamba_main,
                         cudaFuncAttributeMaxDynamicSharedMemorySize,
                         smem_bytes);
    mamba_main<<<NBLK, CH, smem_bytes>>>(P);
}

// round 11
// speedup vs baseline: 1.0009x; 1.0009x over previous
#include <cuda_runtime.h>

#define TT   300
#define LSEQ 30
#define CH   128
#define NS   16
#define NR   8
#define NBLK (8 * 300)

// Precomputed fused epilogue weights: M_dir = Wout_dir @ comb_W_half, and
// constant vector cvec = comb_b + f_bout@comb_W[:128] + b_bout@comb_W[128:].
__device__ float g_Mf[CH * CH];
__device__ float g_Mb[CH * CH];
__device__ float g_cvec[CH];

struct DirParams {
    const float *Win, *bin, *convw, *convb, *Wx, *Wdt, *bdt, *Alog, *D;
};

struct KParams {
    const float *x, *ln_g, *ln_b;
    DirParams dp[2];
    float *out;
};

// ---------------------------------------------------------------------------
// Precompute kernel: M_f[d][c] = sum_j Wout_f[d][j] * comb_W[j][c]
//                    M_b[d][c] = sum_j Wout_b[d][j] * comb_W[128+j][c]
// ---------------------------------------------------------------------------
__global__ void precompute_kernel(const float* __restrict__ fWout,
                                  const float* __restrict__ bWout,
                                  const float* __restrict__ combW,
                                  const float* __restrict__ combb,
                                  const float* __restrict__ fbout,
                                  const float* __restrict__ bbout) {
    int dd = blockIdx.x;
    int c  = threadIdx.x;
    float af = 0.f, ab = 0.f;
    for (int j = 0; j < CH; ++j) {
        float cw_top = combW[j * CH + c];
        float cw_bot = combW[(CH + j) * CH + c];
        af = fmaf(fWout[dd * CH + j], cw_top, af);
        ab = fmaf(bWout[dd * CH + j], cw_bot, ab);
    }
    g_Mf[dd * CH + c] = af;
    g_Mb[dd * CH + c] = ab;
    if (dd == 0) {
        float cv = combb[c];
        for (int j = 0; j < CH; ++j) {
            cv = fmaf(fbout[j], combW[j * CH + c], cv);
            cv = fmaf(bbout[j], combW[(CH + j) * CH + c], cv);
        }
        g_cvec[c] = cv;
    }
}

// ---------------------------------------------------------------------------
// Per-direction processing. BACK=true runs the backward (flipped) direction
// without physically flipping data: anti-causal conv + reverse-order scan.
// ---------------------------------------------------------------------------
template <bool BACK>
__device__ __forceinline__ void process_dir(const DirParams& P,
                                            const float* __restrict__ Mfused,
                                            float* s_xn, float* s_xp,
                                            float* s_y, float* s_xdbl,
                                            float* s_acc, int d) {
    const float* __restrict__ Win = P.Win;
    float zreg[LSEQ];  // silu(z), kept in registers (static-index only)

    // ---- xz = xn @ Win + bin ; xp -> smem, silu(z) -> regs -----------------
    const float binx = P.bin[d];
    const float binz = P.bin[CH + d];
#pragma unroll
    for (int chunk = 0; chunk < 2; ++chunk) {
        float ax[15], az[15];
#pragma unroll
        for (int i = 0; i < 15; ++i) { ax[i] = 0.f; az[i] = 0.f; }
        const float4* xn4 =
            reinterpret_cast<const float4*>(s_xn + chunk * 15 * CH);
        for (int c4 = 0; c4 < 32; ++c4) {
            const float* wp = Win + c4 * 4 * 256 + d;
            float wx0 = wp[0];         float wz0 = wp[128];
            float wx1 = wp[256];       float wz1 = wp[256 + 128];
            float wx2 = wp[512];       float wz2 = wp[512 + 128];
            float wx3 = wp[768];       float wz3 = wp[768 + 128];
#pragma unroll
            for (int i = 0; i < 15; ++i) {
                float4 v = xn4[i * 32 + c4];
                ax[i] = fmaf(v.x, wx0, ax[i]); az[i] = fmaf(v.x, wz0, az[i]);
                ax[i] = fmaf(v.y, wx1, ax[i]); az[i] = fmaf(v.y, wz1, az[i]);
                ax[i] = fmaf(v.z, wx2, ax[i]); az[i] = fmaf(v.z, wz2, az[i]);
                ax[i] = fmaf(v.w, wx3, ax[i]); az[i] = fmaf(v.w, wz3, az[i]);
            }
        }
#pragma unroll
        for (int i = 0; i < 15; ++i) {
            int l = chunk * 15 + i;
            s_xp[l * CH + d] = ax[i] + binx;
            float zv = az[i] + binz;
            zreg[l] = zv / (1.f + __expf(-zv));
        }
    }

    // ---- depthwise causal conv + silu (own column only, no sync needed) ---
    {
        float cw0 = P.convw[d * 4 + 0], cw1 = P.convw[d * 4 + 1];
        float cw2 = P.convw[d * 4 + 2], cw3 = P.convw[d * 4 + 3];
        float cb = P.convb[d];
        if (!BACK) {
            float w0 = 0.f, w1 = 0.f, w2 = 0.f;
#pragma unroll
            for (int l = 0; l < LSEQ; ++l) {
                float cur = s_xp[l * CH + d];
                float xc = cb + cw0 * w0 + cw1 * w1 + cw2 * w2 + cw3 * cur;
                w0 = w1; w1 = w2; w2 = cur;
                s_xp[l * CH + d] = xc / (1.f + __expf(-xc));
            }
        } else {
            // flipped causal conv == anti-causal conv with reversed taps
            float f1 = 0.f, f2 = 0.f, f3 = 0.f;
#pragma unroll
            for (int l = LSEQ - 1; l >= 0; --l) {
                float cur = s_xp[l * CH + d];
                float xc = cb + cw3 * cur + cw2 * f1 + cw1 * f2 + cw0 * f3;
                f3 = f2; f2 = f1; f1 = cur;
                s_xp[l * CH + d] = xc / (1.f + __expf(-xc));
            }
        }
    }
    __syncthreads();

    // ---- xdbl = xp @ Wx  (40 output cols: dtr[8] | B[16] | C[16]) ----------
    if (d < 120) {
        int g = d / 40, col = d % 40;
        const float* __restrict__ Wx = P.Wx;
        float acc[10];
#pragma unroll
        for (int i = 0; i < 10; ++i) acc[i] = 0.f;
        const float4* xp4 =
            reinterpret_cast<const float4*>(s_xp + g * 10 * CH);
        for (int c4 = 0; c4 < 32; ++c4) {
            float w0 = Wx[(c4 * 4 + 0) * 40 + col];
            float w1 = Wx[(c4 * 4 + 1) * 40 + col];
            float w2 = Wx[(c4 * 4 + 2) * 40 + col];
            float w3 = Wx[(c4 * 4 + 3) * 40 + col];
#pragma unroll
            for (int i = 0; i < 10; ++i) {
                float4 v = xp4[i * 32 + c4];
                acc[i] = fmaf(v.x, w0,
                         fmaf(v.y, w1, fmaf(v.z, w2, fmaf(v.w, w3, acc[i]))));
            }
        }
#pragma unroll
        for (int i = 0; i < 10; ++i)
            s_xdbl[(g * 10 + i) * 40 + col] = acc[i];
    }
    __syncthreads();

    // ---- dt = softplus(dtr @ Wdt + bdt), staged into s_y -------------------
    {
        float wdt[NR];
#pragma unroll
        for (int r = 0; r < NR; ++r) wdt[r] = P.Wdt[r * CH + d];
        float bdtv = P.bdt[d];
#pragma unroll
        for (int l = 0; l < LSEQ; ++l) {
            const float4* row =
                reinterpret_cast<const float4*>(s_xdbl + l * 40);
            float4 r0 = row[0], r1 = row[1];
            float acc = bdtv;
            acc = fmaf(r0.x, wdt[0], acc); acc = fmaf(r0.y, wdt[1], acc);
            acc = fmaf(r0.z, wdt[2], acc); acc = fmaf(r0.w, wdt[3], acc);
            acc = fmaf(r1.x, wdt[4], acc); acc = fmaf(r1.y, wdt[5], acc);
            acc = fmaf(r1.z, wdt[6], acc); acc = fmaf(r1.w, wdt[7], acc);
            s_y[l * CH + d] = (acc > 20.f) ? acc : log1pf(__expf(acc));
        }
    }

    // ---- selective scan (sequential over L, 16 states in registers) -------
    {
        float Areg[NS];
#pragma unroll
        for (int s = 0; s < NS; ++s) Areg[s] = -expf(P.Alog[d * NS + s]);
        float Dp = P.D[d];
        float h[NS];
#pragma unroll
        for (int s = 0; s < NS; ++s) h[s] = 0.f;
        for (int it = 0; it < LSEQ; ++it) {
            int l = BACK ? (LSEQ - 1 - it) : it;
            float dt_t = s_y[l * CH + d];     // staged dt
            float x_t  = s_xp[l * CH + d];
            float dtx  = dt_t * x_t;
            const float4* bc =
                reinterpret_cast<const float4*>(s_xdbl + l * 40 + 8);
            float4 B0 = bc[0], B1 = bc[1], B2 = bc[2], B3 = bc[3];
            float4 C0 = bc[4], C1 = bc[5], C2 = bc[6], C3 = bc[7];
            float y = 0.f;
#define SSTEP(s, Bv, Cv)                                 \
    {                                                    \
        float dA_ = __expf(dt_t * Areg[s]);              \
        h[s] = fmaf(dA_, h[s], dtx * (Bv));              \
        y = fmaf(h[s], (Cv), y);                         \
    }
            SSTEP(0,  B0.x, C0.x) SSTEP(1,  B0.y, C0.y)
            SSTEP(2,  B0.z, C0.z) SSTEP(3,  B0.w, C0.w)
            SSTEP(4,  B1.x, C1.x) SSTEP(5,  B1.y, C1.y)
            SSTEP(6,  B1.z, C1.z) SSTEP(7,  B1.w, C1.w)
            SSTEP(8,  B2.x, C2.x) SSTEP(9,  B2.y, C2.y)
            SSTEP(10, B2.z, C2.z) SSTEP(11, B2.w, C2.w)
            SSTEP(12, B3.x, C3.x) SSTEP(13, B3.y, C3.y)
            SSTEP(14, B3.z, C3.z) SSTEP(15, B3.w, C3.w)
#undef SSTEP
            s_y[l * CH + d] = fmaf(x_t, Dp, y);  // + skip via D
        }
    }

    // ---- gate by silu(z) (static-index loop keeps zreg in regs) -----------
#pragma unroll
    for (int l = 0; l < LSEQ; ++l) s_y[l * CH + d] *= zreg[l];
    __syncthreads();

    // ---- fused epilogue: s_acc += s_y @ (Wout @ comb_half) ----------------
#pragma unroll
    for (int chunk = 0; chunk < 2; ++chunk) {
        float a[15];
#pragma unroll
        for (int i = 0; i < 15; ++i)
            a[i] = s_acc[(chunk * 15 + i) * CH + d];
        const float4* y4 =
            reinterpret_cast<const float4*>(s_y + chunk * 15 * CH);
        for (int j4 = 0; j4 < 32; ++j4) {
            const float* mp = Mfused + j4 * 4 * CH + d;
            float m0 = mp[0], m1 = mp[CH], m2 = mp[2 * CH], m3 = mp[3 * CH];
#pragma unroll
            for (int i = 0; i < 15; ++i) {
                float4 v = y4[i * 32 + j4];
                a[i] = fmaf(v.x, m0,
                       fmaf(v.y, m1, fmaf(v.z, m2, fmaf(v.w, m3, a[i]))));
            }
        }
#pragma unroll
        for (int i = 0; i < 15; ++i)
            s_acc[(chunk * 15 + i) * CH + d] = a[i];
    }
    __syncthreads();
}

// ---------------------------------------------------------------------------
// Main kernel: one block per (b, t) frame.
// smem: acc[30*128] | xn[30*128] | xp[30*128] | y[30*128] | xdbl[30*40]
// ---------------------------------------------------------------------------
__global__ void __launch_bounds__(128, 3)
mamba_main(KParams P) {
    extern __shared__ float smem[];
    float* s_acc  = smem;              // raw input -> final accumulator
    float* s_xn   = smem + 3840;       // normalized input
    float* s_xp   = smem + 7680;       // xp (pre/post conv+silu)
    float* s_y    = smem + 11520;      // dt staging -> gated scan output
    float* s_xdbl = smem + 15360;      // [30][40] : dtr | B | C

    const int d  = threadIdx.x;
    const int bt = blockIdx.x;
    const int b  = bt / TT;
    const int t  = bt % TT;

    // ---- load x[b, d, t, :] (30 contiguous floats per thread) -------------
    const float2* x2 = reinterpret_cast<const float2*>(
        P.x + ((size_t)(b * CH + d) * TT + t) * LSEQ);
#pragma unroll
    for (int i = 0; i < 15; ++i) {
        float2 v = x2[i];
        s_acc[(2 * i) * CH + d]     = v.x;
        s_acc[(2 * i + 1) * CH + d] = v.y;
    }
    __syncthreads();

    // ---- LayerNorm over the 128 channels of each row -----------------------
    {
        int warp = d >> 5, lane = d & 31;
        float g0 = P.ln_g[lane],      g1 = P.ln_g[lane + 32];
        float g2 = P.ln_g[lane + 64], g3 = P.ln_g[lane + 96];
        float e0 = P.ln_b[lane],      e1 = P.ln_b[lane + 32];
        float e2 = P.ln_b[lane + 64], e3 = P.ln_b[lane + 96];
        for (int l = warp; l < LSEQ; l += 4) {
            float v0 = s_acc[l * CH + lane];
            float v1 = s_acc[l * CH + lane + 32];
            float v2 = s_acc[l * CH + lane + 64];
            float v3 = s_acc[l * CH + lane + 96];
            float sum = v0 + v1 + v2 + v3;
            float sq  = v0 * v0 + v1 * v1 + v2 * v2 + v3 * v3;
#pragma unroll
            for (int off = 16; off > 0; off >>= 1) {
                sum += __shfl_xor_sync(0xffffffffu, sum, off);
                sq  += __shfl_xor_sync(0xffffffffu, sq, off);
            }
            float mu  = sum * (1.f / 128.f);
            float var = sq * (1.f / 128.f) - mu * mu;
            float rs  = rsqrtf(var + 1e-5f);
            s_xn[l * CH + lane]      = (v0 - mu) * rs * g0 + e0;
            s_xn[l * CH + lane + 32] = (v1 - mu) * rs * g1 + e1;
            s_xn[l * CH + lane + 64] = (v2 - mu) * rs * g2 + e2;
            s_xn[l * CH + lane + 96] = (v3 - mu) * rs * g3 + e3;
        }
    }
    __syncthreads();

    process_dir<false>(P.dp[0], g_Mf, s_xn, s_xp, s_y, s_xdbl, s_acc, d);
    process_dir<true >(P.dp[1], g_Mb, s_xn, s_xp, s_y, s_xdbl, s_acc, d);

    // ---- write out (+ fused bias vector) -----------------------------------
    float cv = g_cvec[d];
    float2* o2 = reinterpret_cast<float2*>(
        P.out + ((size_t)(b * CH + d) * TT + t) * LSEQ);
#pragma unroll
    for (int i = 0; i < 15; ++i) {
        float2 v;
        v.x = s_acc[(2 * i) * CH + d] + cv;
        v.y = s_acc[(2 * i + 1) * CH + d] + cv;
        o2[i] = v;
    }
}

// ---------------------------------------------------------------------------
extern "C" void kernel_launch(void* const* d_in, const int* in_sizes, int n_in,
                              void* d_out, int out_size) {
    (void)in_sizes; (void)n_in; (void)out_size;
    KParams P;
    P.x    = (const float*)d_in[0];
    P.ln_g = (const float*)d_in[1];
    P.ln_b = (const float*)d_in[2];
    for (int dir = 0; dir < 2; ++dir) {
        int o = 3 + dir * 11;
        P.dp[dir].Win   = (const float*)d_in[o + 0];
        P.dp[dir].bin   = (const float*)d_in[o + 1];
        P.dp[dir].convw = (const float*)d_in[o + 2];
        P.dp[dir].convb = (const float*)d_in[o + 3];
        P.dp[dir].Wx    = (const float*)d_in[o + 4];
        P.dp[dir].Wdt   = (const float*)d_in[o + 5];
        P.dp[dir].bdt   = (const float*)d_in[o + 6];
        P.dp[dir].Alog  = (const float*)d_in[o + 7];
        P.dp[dir].D     = (const float*)d_in[o + 8];
        // [o+9] = Wout, [o+10] = bout -> consumed by precompute_kernel
    }
    P.out = (float*)d_out;

    // Fuse Wout @ comb_W halves (+ bias folding) once per launch.
    precompute_kernel<<<CH, CH>>>(
        (const float*)d_in[12], (const float*)d_in[23],
        (const float*)d_in[25], (const float*)d_in[26],
        (const float*)d_in[13], (const float*)d_in[24]);

    const int smem_bytes = 16560 * sizeof(float);  // 66240 B
    cudaFuncSetAttribute(mamba_main,
                         cudaFuncAttributeMaxDynamicSharedMemorySize,
                         smem_bytes);
    mamba_main<<<NBLK, CH, smem_bytes>>>(P);
}

// round 12
// speedup vs baseline: 1.0046x; 1.0037x over previous
#include <cuda_runtime.h>

#define TT   300
#define LSEQ 30
#define CH   128
#define NS   16
#define NR   8
#define NBLK (8 * 300)

// Precomputed fused epilogue weights: M_dir = Wout_dir @ comb_W_half, and
// constant vector cvec = comb_b + f_bout@comb_W[:128] + b_bout@comb_W[128:].
__device__ float g_Mf[CH * CH];
__device__ float g_Mb[CH * CH];
__device__ float g_cvec[CH];

struct DirParams {
    const float *Win, *bin, *convw, *convb, *Wx, *Wdt, *bdt, *Alog, *D;
};

struct KParams {
    const float *x, *ln_g, *ln_b;
    DirParams dp[2];
    float *out;
};

// ---------------------------------------------------------------------------
// Precompute kernel: M_f[d][c] = sum_j Wout_f[d][j] * comb_W[j][c]
//                    M_b[d][c] = sum_j Wout_b[d][j] * comb_W[128+j][c]
// ---------------------------------------------------------------------------
__global__ void precompute_kernel(const float* __restrict__ fWout,
                                  const float* __restrict__ bWout,
                                  const float* __restrict__ combW,
                                  const float* __restrict__ combb,
                                  const float* __restrict__ fbout,
                                  const float* __restrict__ bbout) {
    int dd = blockIdx.x;
    int c  = threadIdx.x;
    float af = 0.f, ab = 0.f;
    for (int j = 0; j < CH; ++j) {
        float cw_top = combW[j * CH + c];
        float cw_bot = combW[(CH + j) * CH + c];
        af = fmaf(fWout[dd * CH + j], cw_top, af);
        ab = fmaf(bWout[dd * CH + j], cw_bot, ab);
    }
    g_Mf[dd * CH + c] = af;
    g_Mb[dd * CH + c] = ab;
    if (dd == 0) {
        float cv = combb[c];
        for (int j = 0; j < CH; ++j) {
            cv = fmaf(fbout[j], combW[j * CH + c], cv);
            cv = fmaf(bbout[j], combW[(CH + j) * CH + c], cv);
        }
        g_cvec[c] = cv;
    }
}

// ---------------------------------------------------------------------------
// Per-direction processing. BACK=true runs the backward (flipped) direction
// without physically flipping data: anti-causal conv + reverse-order scan.
// ---------------------------------------------------------------------------
template <bool BACK>
__device__ __forceinline__ void process_dir(const DirParams& P,
                                            const float* __restrict__ Mfused,
                                            float* s_xn, float* s_xp,
                                            float* s_y, float* s_xdbl,
                                            float* s_acc, int d) {
    const float* __restrict__ Win = P.Win;
    float zreg[LSEQ];  // silu(z), kept in registers (static-index only)

    // ---- xz = xn @ Win + bin ; xp -> smem, silu(z) -> regs -----------------
    const float binx = P.bin[d];
    const float binz = P.bin[CH + d];
#pragma unroll
    for (int chunk = 0; chunk < 2; ++chunk) {
        float ax[15], az[15];
#pragma unroll
        for (int i = 0; i < 15; ++i) { ax[i] = 0.f; az[i] = 0.f; }
        const float4* xn4 =
            reinterpret_cast<const float4*>(s_xn + chunk * 15 * CH);
        for (int c4 = 0; c4 < 32; ++c4) {
            const float* wp = Win + c4 * 4 * 256 + d;
            float wx0 = wp[0];         float wz0 = wp[128];
            float wx1 = wp[256];       float wz1 = wp[256 + 128];
            float wx2 = wp[512];       float wz2 = wp[512 + 128];
            float wx3 = wp[768];       float wz3 = wp[768 + 128];
#pragma unroll
            for (int i = 0; i < 15; ++i) {
                float4 v = xn4[i * 32 + c4];
                ax[i] = fmaf(v.x, wx0, ax[i]); az[i] = fmaf(v.x, wz0, az[i]);
                ax[i] = fmaf(v.y, wx1, ax[i]); az[i] = fmaf(v.y, wz1, az[i]);
                ax[i] = fmaf(v.z, wx2, ax[i]); az[i] = fmaf(v.z, wz2, az[i]);
                ax[i] = fmaf(v.w, wx3, ax[i]); az[i] = fmaf(v.w, wz3, az[i]);
            }
        }
#pragma unroll
        for (int i = 0; i < 15; ++i) {
            int l = chunk * 15 + i;
            s_xp[l * CH + d] = ax[i] + binx;
            float zv = az[i] + binz;
            zreg[l] = zv / (1.f + __expf(-zv));
        }
    }

    // ---- depthwise causal conv + silu (own column only, no sync needed) ---
    {
        float cw0 = P.convw[d * 4 + 0], cw1 = P.convw[d * 4 + 1];
        float cw2 = P.convw[d * 4 + 2], cw3 = P.convw[d * 4 + 3];
        float cb = P.convb[d];
        if (!BACK) {
            float w0 = 0.f, w1 = 0.f, w2 = 0.f;
#pragma unroll
            for (int l = 0; l < LSEQ; ++l) {
                float cur = s_xp[l * CH + d];
                float xc = cb + cw0 * w0 + cw1 * w1 + cw2 * w2 + cw3 * cur;
                w0 = w1; w1 = w2; w2 = cur;
                s_xp[l * CH + d] = xc / (1.f + __expf(-xc));
            }
        } else {
            // flipped causal conv == anti-causal conv with reversed taps
            float f1 = 0.f, f2 = 0.f, f3 = 0.f;
#pragma unroll
            for (int l = LSEQ - 1; l >= 0; --l) {
                float cur = s_xp[l * CH + d];
                float xc = cb + cw3 * cur + cw2 * f1 + cw1 * f2 + cw0 * f3;
                f3 = f2; f2 = f1; f1 = cur;
                s_xp[l * CH + d] = xc / (1.f + __expf(-xc));
            }
        }
    }
    __syncthreads();

    // ---- xdbl = xp @ Wx  (40 output cols: dtr[8] | B[16] | C[16]) ----------
    if (d < 120) {
        int g = d / 40, col = d % 40;
        const float* __restrict__ Wx = P.Wx;
        float acc[10];
#pragma unroll
        for (int i = 0; i < 10; ++i) acc[i] = 0.f;
        const float4* xp4 =
            reinterpret_cast<const float4*>(s_xp + g * 10 * CH);
        for (int c4 = 0; c4 < 32; ++c4) {
            float w0 = Wx[(c4 * 4 + 0) * 40 + col];
            float w1 = Wx[(c4 * 4 + 1) * 40 + col];
            float w2 = Wx[(c4 * 4 + 2) * 40 + col];
            float w3 = Wx[(c4 * 4 + 3) * 40 + col];
#pragma unroll
            for (int i = 0; i < 10; ++i) {
                float4 v = xp4[i * 32 + c4];
                acc[i] = fmaf(v.x, w0,
                         fmaf(v.y, w1, fmaf(v.z, w2, fmaf(v.w, w3, acc[i]))));
            }
        }
#pragma unroll
        for (int i = 0; i < 10; ++i)
            s_xdbl[(g * 10 + i) * 40 + col] = acc[i];
    }
    __syncthreads();

    // ---- dt = softplus(dtr @ Wdt + bdt), staged into s_y -------------------
    {
        float wdt[NR];
#pragma unroll
        for (int r = 0; r < NR; ++r) wdt[r] = P.Wdt[r * CH + d];
        float bdtv = P.bdt[d];
#pragma unroll
        for (int l = 0; l < LSEQ; ++l) {
            const float4* row =
                reinterpret_cast<const float4*>(s_xdbl + l * 40);
            float4 r0 = row[0], r1 = row[1];
            float acc = bdtv;
            acc = fmaf(r0.x, wdt[0], acc); acc = fmaf(r0.y, wdt[1], acc);
            acc = fmaf(r0.z, wdt[2], acc); acc = fmaf(r0.w, wdt[3], acc);
            acc = fmaf(r1.x, wdt[4], acc); acc = fmaf(r1.y, wdt[5], acc);
            acc = fmaf(r1.z, wdt[6], acc); acc = fmaf(r1.w, wdt[7], acc);
            s_y[l * CH + d] = (acc > 20.f) ? acc : log1pf(__expf(acc));
        }
    }

    // ---- selective scan (sequential over L, 16 states in registers) -------
    {
        float Areg[NS];
#pragma unroll
        for (int s = 0; s < NS; ++s) Areg[s] = -expf(P.Alog[d * NS + s]);
        float Dp = P.D[d];
        float h[NS];
#pragma unroll
        for (int s = 0; s < NS; ++s) h[s] = 0.f;
        for (int it = 0; it < LSEQ; ++it) {
            int l = BACK ? (LSEQ - 1 - it) : it;
            float dt_t = s_y[l * CH + d];     // staged dt
            float x_t  = s_xp[l * CH + d];
            float dtx  = dt_t * x_t;
            const float4* bc =
                reinterpret_cast<const float4*>(s_xdbl + l * 40 + 8);
            float4 B0 = bc[0], B1 = bc[1], B2 = bc[2], B3 = bc[3];
            float4 C0 = bc[4], C1 = bc[5], C2 = bc[6], C3 = bc[7];
            float y = 0.f;
#define SSTEP(s, Bv, Cv)                                 \
    {                                                    \
        float dA_ = __expf(dt_t * Areg[s]);              \
        h[s] = fmaf(dA_, h[s], dtx * (Bv));              \
        y = fmaf(h[s], (Cv), y);                         \
    }
            SSTEP(0,  B0.x, C0.x) SSTEP(1,  B0.y, C0.y)
            SSTEP(2,  B0.z, C0.z) SSTEP(3,  B0.w, C0.w)
            SSTEP(4,  B1.x, C1.x) SSTEP(5,  B1.y, C1.y)
            SSTEP(6,  B1.z, C1.z) SSTEP(7,  B1.w, C1.w)
            SSTEP(8,  B2.x, C2.x) SSTEP(9,  B2.y, C2.y)
            SSTEP(10, B2.z, C2.z) SSTEP(11, B2.w, C2.w)
            SSTEP(12, B3.x, C3.x) SSTEP(13, B3.y, C3.y)
            SSTEP(14, B3.z, C3.z) SSTEP(15, B3.w, C3.w)
#undef SSTEP
            s_y[l * CH + d] = fmaf(x_t, Dp, y);  // + skip via D
        }
    }

    // ---- gate by silu(z) (static-index loop keeps zreg in regs) -----------
#pragma unroll
    for (int l = 0; l < LSEQ; ++l) s_y[l * CH + d] *= zreg[l];
    __syncthreads();

    // ---- fused epilogue: s_acc += s_y @ (Wout @ comb_half) ----------------
#pragma unroll
    for (int chunk = 0; chunk < 2; ++chunk) {
        float a[15];
#pragma unroll
        for (int i = 0; i < 15; ++i)
            a[i] = s_acc[(chunk * 15 + i) * CH + d];
        const float4* y4 =
            reinterpret_cast<const float4*>(s_y + chunk * 15 * CH);
        for (int j4 = 0; j4 < 32; ++j4) {
            const float* mp = Mfused + j4 * 4 * CH + d;
            float m0 = mp[0], m1 = mp[CH], m2 = mp[2 * CH], m3 = mp[3 * CH];
#pragma unroll
            for (int i = 0; i < 15; ++i) {
                float4 v = y4[i * 32 + j4];
                a[i] = fmaf(v.x, m0,
                       fmaf(v.y, m1, fmaf(v.z, m2, fmaf(v.w, m3, a[i]))));
            }
        }
#pragma unroll
        for (int i = 0; i < 15; ++i)
            s_acc[(chunk * 15 + i) * CH + d] = a[i];
    }
    __syncthreads();
}

// ---------------------------------------------------------------------------
// Main kernel: one block per (b, t) frame.
// smem: acc[30*128] | xn[30*128] | xp[30*128] | y[30*128] | xdbl[30*40]
// ---------------------------------------------------------------------------
__global__ void __launch_bounds__(128, 3)
mamba_main(KParams P) {
    extern __shared__ float smem[];
    float* s_acc  = smem;              // raw input -> final accumulator
    float* s_xn   = smem + 3840;       // normalized input
    float* s_xp   = smem + 7680;       // xp (pre/post conv+silu)
    float* s_y    = smem + 11520;      // dt staging -> gated scan output
    float* s_xdbl = smem + 15360;      // [30][40] : dtr | B | C

    const int d  = threadIdx.x;
    const int bt = blockIdx.x;
    const int b  = bt / TT;
    const int t  = bt % TT;

    // ---- load x[b, d, t, :] (30 contiguous floats per thread) -------------
    const float2* x2 = reinterpret_cast<const float2*>(
        P.x + ((size_t)(b * CH + d) * TT + t) * LSEQ);
#pragma unroll
    for (int i = 0; i < 15; ++i) {
        float2 v = x2[i];
        s_acc[(2 * i) * CH + d]     = v.x;
        s_acc[(2 * i + 1) * CH + d] = v.y;
    }
    __syncthreads();

    // ---- LayerNorm over the 128 channels of each row -----------------------
    {
        int warp = d >> 5, lane = d & 31;
        float g0 = P.ln_g[lane],      g1 = P.ln_g[lane + 32];
        float g2 = P.ln_g[lane + 64], g3 = P.ln_g[lane + 96];
        float e0 = P.ln_b[lane],      e1 = P.ln_b[lane + 32];
        float e2 = P.ln_b[lane + 64], e3 = P.ln_b[lane + 96];
        for (int l = warp; l < LSEQ; l += 4) {
            float v0 = s_acc[l * CH + lane];
            float v1 = s_acc[l * CH + lane + 32];
            float v2 = s_acc[l * CH + lane + 64];
            float v3 = s_acc[l * CH + lane + 96];
            float sum = v0 + v1 + v2 + v3;
            float sq  = v0 * v0 + v1 * v1 + v2 * v2 + v3 * v3;
#pragma unroll
            for (int off = 16; off > 0; off >>= 1) {
                sum += __shfl_xor_sync(0xffffffffu, sum, off);
                sq  += __shfl_xor_sync(0xffffffffu, sq, off);
            }
            float mu  = sum * (1.f / 128.f);
            float var = sq * (1.f / 128.f) - mu * mu;
            float rs  = rsqrtf(var + 1e-5f);
            s_xn[l * CH + lane]      = (v0 - mu) * rs * g0 + e0;
            s_xn[l * CH + lane + 32] = (v1 - mu) * rs * g1 + e1;
            s_xn[l * CH + lane + 64] = (v2 - mu) * rs * g2 + e2;
            s_xn[l * CH + lane + 96] = (v3 - mu) * rs * g3 + e3;
        }
    }
    __syncthreads();

    process_dir<false>(P.dp[0], g_Mf, s_xn, s_xp, s_y, s_xdbl, s_acc, d);
    process_dir<true >(P.dp[1], g_Mb, s_xn, s_xp, s_y, s_xdbl, s_acc, d);

    // ---- write out (+ fused bias vector) -----------------------------------
    float cv = g_cvec[d];
    float2* o2 = reinterpret_cast<float2*>(
        P.out + ((size_t)(b * CH + d) * TT + t) * LSEQ);
#pragma unroll
    for (int i = 0; i < 15; ++i) {
        float2 v;
        v.x = s_acc[(2 * i) * CH + d] + cv;
        v.y = s_acc[(2 * i + 1) * CH + d] + cv;
        o2[i] = v;
    }
}

// ---------------------------------------------------------------------------
extern "C" void kernel_launch(void* const* d_in, const int* in_sizes, int n_in,
                              void* d_out, int out_size) {
    (void)in_sizes; (void)n_in; (void)out_size;
    KParams P;
    P.x    = (const float*)d_in[0];
    P.ln_g = (const float*)d_in[1];
    P.ln_b = (const float*)d_in[2];
    for (int dir = 0; dir < 2; ++dir) {
        int o = 3 + dir * 11;
        P.dp[dir].Win   = (const float*)d_in[o + 0];
        P.dp[dir].bin   = (const float*)d_in[o + 1];
        P.dp[dir].convw = (const float*)d_in[o + 2];
        P.dp[dir].convb = (const float*)d_in[o + 3];
        P.dp[dir].Wx    = (const float*)d_in[o + 4];
        P.dp[dir].Wdt   = (const float*)d_in[o + 5];
        P.dp[dir].bdt   = (const float*)d_in[o + 6];
        P.dp[dir].Alog  = (const float*)d_in[o + 7];
        P.dp[dir].D     = (const float*)d_in[o + 8];
        // [o+9] = Wout, [o+10] = bout -> consumed by precompute_kernel
    }
    P.out = (float*)d_out;

    // Fuse Wout @ comb_W halves (+ bias folding) once per launch.
    precompute_kernel<<<CH, CH>>>(
        (const float*)d_in[12], (const float*)d_in[23],
        (const float*)d_in[25], (const float*)d_in[26],
        (const float*)d_in[13], (const float*)d_in[24]);

    const int smem_bytes = 16560 * sizeof(float);  // 66240 B
    cudaFuncSetAttribute(mamba_main,
                         cudaFuncAttributeMaxDynamicSharedMemorySize,
                         smem_bytes);
    mamba_main<<<NBLK, CH, smem_bytes>>>(P);
}